// round 1
// baseline (speedup 1.0000x reference)
#include <cuda_runtime.h>
#include <math.h>

// ---------------------------------------------------------------------------
// SlotAttention: b=32, n=1024, c=256, d=256, S=8 slots, 3 iters. All fp32.
// ---------------------------------------------------------------------------
#define Bsz 32
#define NTOK 1024
#define Cdim 256
#define Ddim 256
#define NSLOT 8
#define ITERS 3
#define TOKROWS (Bsz*NTOK)      // 32768
#define SROWS (Bsz*NSLOT)       // 256
#define SCALE_F 0.0625f         // 256^-0.5
#define EPS_F 1e-8f

// scratch arena offsets (floats)
#define OFF_STATS 0                            // 32768*2
#define OFF_K     (OFF_STATS + TOKROWS*2)      // 32768*256
#define OFF_V     (OFF_K + TOKROWS*Ddim)
#define OFF_SLOTS (OFF_V + TOKROWS*Ddim)       // 256*256
#define OFF_SLN   (OFF_SLOTS + SROWS*Ddim)
#define OFF_Q     (OFF_SLN + SROWS*Ddim)
#define OFF_ATTN  (OFF_Q + SROWS*Ddim)         // 32*1024*8
#define OFF_UPDP  (OFF_ATTN + Bsz*NTOK*NSLOT)  // 4*256*256
#define OFF_RSP   (OFF_UPDP + 4*SROWS*Ddim)    // 4*256
#define OFF_U     (OFF_RSP + 4*SROWS)
#define OFF_GI    (OFF_U + SROWS*Ddim)         // 256*768
#define OFF_GH    (OFF_GI + SROWS*3*Ddim)
#define OFF_H1    (OFF_GH + SROWS*3*Ddim)      // 256*1024
#define OFF_FF    (OFF_H1 + SROWS*4*Ddim)
#define SCRATCH_FLOATS (OFF_FF + SROWS*Ddim)

__device__ float g_scratch[SCRATCH_FLOATS];

__device__ __forceinline__ float warp_sum(float v) {
#pragma unroll
    for (int o = 16; o > 0; o >>= 1) v += __shfl_xor_sync(0xffffffffu, v, o);
    return v;
}

// slots = mu + exp(log_sigma) * noise
__global__ void init_slots_kernel(const float* __restrict__ mu,
                                  const float* __restrict__ ls,
                                  const float* __restrict__ noise,
                                  float* __restrict__ slots) {
    int idx = blockIdx.x * blockDim.x + threadIdx.x;
    if (idx < SROWS * Ddim) {
        int d = idx & (Ddim - 1);
        slots[idx] = mu[d] + __expf(ls[d]) * noise[idx];
    }
}

// per-token-row mean/rstd of inputs
__global__ void ln_stats_kernel(const float* __restrict__ x, float* __restrict__ stats) {
    int row = blockIdx.x;
    int tid = threadIdx.x;
    float v = x[row * Cdim + tid];
    float s = warp_sum(v);
    float s2 = warp_sum(v * v);
    __shared__ float sh[16];
    int w = tid >> 5, l = tid & 31;
    if (l == 0) { sh[w] = s; sh[8 + w] = s2; }
    __syncthreads();
    if (tid == 0) {
        float S = 0.f, S2 = 0.f;
#pragma unroll
        for (int i = 0; i < 8; i++) { S += sh[i]; S2 += sh[8 + i]; }
        float m = S * (1.0f / 256.0f);
        float var = S2 * (1.0f / 256.0f) - m * m;
        stats[row * 2] = m;
        stats[row * 2 + 1] = rsqrtf(var + 1e-5f);
    }
}

// fused: K = LN(x) @ Wk^T ; V = LN(x) @ Wv^T   (M=32768, N=256, K=256)
__global__ void kv_gemm_kernel(const float* __restrict__ x, const float* __restrict__ stats,
                               const float* __restrict__ lng, const float* __restrict__ lnb,
                               const float* __restrict__ Wk, const float* __restrict__ Wv,
                               float* __restrict__ Kout, float* __restrict__ Vout) {
    __shared__ float As[32][64];
    __shared__ float Bk[32][64];
    __shared__ float Bv[32][64];
    int tid = threadIdx.x;
    int bn = blockIdx.x * 64, bm = blockIdx.y * 64;
    int tr = tid >> 4, tc = tid & 15;
    float accK[4][4]; float accV[4][4];
#pragma unroll
    for (int i = 0; i < 4; i++)
#pragma unroll
        for (int j = 0; j < 4; j++) { accK[i][j] = 0.f; accV[i][j] = 0.f; }

    for (int k0 = 0; k0 < 256; k0 += 32) {
#pragma unroll
        for (int i = 0; i < 8; i++) {
            int l = tid + i * 256;
            int m = l >> 5, kk = l & 31;
            int row = bm + m, c = k0 + kk;
            float mv = stats[row * 2], rstd = stats[row * 2 + 1];
            As[kk][m] = (x[row * 256 + c] - mv) * rstd * lng[c] + lnb[c];
            Bk[kk][m] = Wk[(bn + m) * 256 + c];
            Bv[kk][m] = Wv[(bn + m) * 256 + c];
        }
        __syncthreads();
#pragma unroll
        for (int kk = 0; kk < 32; kk++) {
            float a[4], bk[4], bv[4];
#pragma unroll
            for (int i = 0; i < 4; i++) a[i] = As[kk][tr * 4 + i];
#pragma unroll
            for (int j = 0; j < 4; j++) { bk[j] = Bk[kk][tc * 4 + j]; bv[j] = Bv[kk][tc * 4 + j]; }
#pragma unroll
            for (int i = 0; i < 4; i++)
#pragma unroll
                for (int j = 0; j < 4; j++) {
                    accK[i][j] += a[i] * bk[j];
                    accV[i][j] += a[i] * bv[j];
                }
        }
        __syncthreads();
    }
#pragma unroll
    for (int i = 0; i < 4; i++)
#pragma unroll
        for (int j = 0; j < 4; j++) {
            int row = bm + tr * 4 + i, col = bn + tc * 4 + j;
            Kout[row * 256 + col] = accK[i][j];
            Vout[row * 256 + col] = accV[i][j];
        }
}

// generic C[M,N] = A[M,K] @ B[N,K]^T (+bias, optional relu); BM=BN=64, BK=32
template <bool RELU>
__global__ void gemm_nt_kernel(const float* __restrict__ A, const float* __restrict__ B,
                               const float* __restrict__ bias, float* __restrict__ C,
                               int M, int N, int K) {
    __shared__ float As[32][64];
    __shared__ float Bs[32][64];
    int tid = threadIdx.x;
    int bn = blockIdx.x * 64, bm = blockIdx.y * 64;
    int tr = tid >> 4, tc = tid & 15;
    float acc[4][4];
#pragma unroll
    for (int i = 0; i < 4; i++)
#pragma unroll
        for (int j = 0; j < 4; j++) acc[i][j] = 0.f;

    for (int k0 = 0; k0 < K; k0 += 32) {
#pragma unroll
        for (int i = 0; i < 8; i++) {
            int l = tid + i * 256;
            int m = l >> 5, kk = l & 31;
            As[kk][m] = A[(bm + m) * K + k0 + kk];
            Bs[kk][m] = B[(bn + m) * K + k0 + kk];
        }
        __syncthreads();
#pragma unroll
        for (int kk = 0; kk < 32; kk++) {
            float a[4], bv[4];
#pragma unroll
            for (int i = 0; i < 4; i++) a[i] = As[kk][tr * 4 + i];
#pragma unroll
            for (int j = 0; j < 4; j++) bv[j] = Bs[kk][tc * 4 + j];
#pragma unroll
            for (int i = 0; i < 4; i++)
#pragma unroll
                for (int j = 0; j < 4; j++) acc[i][j] += a[i] * bv[j];
        }
        __syncthreads();
    }
#pragma unroll
    for (int i = 0; i < 4; i++)
#pragma unroll
        for (int j = 0; j < 4; j++) {
            int row = bm + tr * 4 + i, col = bn + tc * 4 + j;
            float v = acc[i][j];
            if (bias) v += bias[col];
            if (RELU) v = fmaxf(v, 0.f);
            C[row * N + col] = v;
        }
}

// LayerNorm over 256-wide rows, writes normalized row
__global__ void ln_rows_kernel(const float* __restrict__ in, float* __restrict__ out,
                               const float* __restrict__ g, const float* __restrict__ b) {
    int row = blockIdx.x;
    int tid = threadIdx.x;
    float v = in[row * 256 + tid];
    float s = warp_sum(v);
    float s2 = warp_sum(v * v);
    __shared__ float sh[16];
    __shared__ float sm, sr;
    int w = tid >> 5, l = tid & 31;
    if (l == 0) { sh[w] = s; sh[8 + w] = s2; }
    __syncthreads();
    if (tid == 0) {
        float S = 0.f, S2 = 0.f;
#pragma unroll
        for (int i = 0; i < 8; i++) { S += sh[i]; S2 += sh[8 + i]; }
        float m = S * (1.0f / 256.0f);
        float var = S2 * (1.0f / 256.0f) - m * m;
        sm = m; sr = rsqrtf(var + 1e-5f);
    }
    __syncthreads();
    out[row * 256 + tid] = (v - sm) * sr * g[tid] + b[tid];
}

// dots[b,i,j] = SCALE * q[b,i,:].k[b,j,:]; softmax over i (8 slots) per (b,j);
// writes attnT[b][j][i] = softmax + EPS (unnormalized over j)
__global__ void dots_softmax_kernel(const float* __restrict__ q, const float* __restrict__ k,
                                    float* __restrict__ attnT) {
    int b = blockIdx.x;
    int tid = threadIdx.x;
    __shared__ float qs[NSLOT * 256];
    for (int i = tid; i < NSLOT * 256; i += 256) qs[i] = q[b * NSLOT * 256 + i] * SCALE_F;
    __syncthreads();
    int wid = tid >> 5, lane = tid & 31;
    int j = blockIdx.y * 8 + wid;
    const float* krow = &k[(b * NTOK + j) * 256];
    float kr[8];
#pragma unroll
    for (int u = 0; u < 8; u++) kr[u] = krow[u * 32 + lane];
    float dv[NSLOT];
#pragma unroll
    for (int i = 0; i < NSLOT; i++) {
        float p = 0.f;
#pragma unroll
        for (int u = 0; u < 8; u++) p += qs[i * 256 + u * 32 + lane] * kr[u];
        p = warp_sum(p);
        dv[i] = p;
    }
    float mx = dv[0];
#pragma unroll
    for (int i = 1; i < NSLOT; i++) mx = fmaxf(mx, dv[i]);
    float se = 0.f;
    float ev[NSLOT];
#pragma unroll
    for (int i = 0; i < NSLOT; i++) { ev[i] = __expf(dv[i] - mx); se += ev[i]; }
    float inv = 1.0f / se;
    float my = 0.f;
#pragma unroll
    for (int i = 0; i < NSLOT; i++) {
        float a = ev[i] * inv + EPS_F;
        if (lane == i) my = a;
    }
    if (lane < NSLOT) attnT[(b * NTOK + j) * NSLOT + lane] = my;
}

// partial updates: raw sum over a 256-wide j range, + partial rowsums
__global__ void updates_part_kernel(const float* __restrict__ attnT, const float* __restrict__ v,
                                    float* __restrict__ updp, float* __restrict__ rsp) {
    int b = blockIdx.x;
    int p = blockIdx.y;
    int tid = threadIdx.x;
    int j0 = p * 256;
    __shared__ float sa[128 * NSLOT];
    float acc[NSLOT];
#pragma unroll
    for (int i = 0; i < NSLOT; i++) acc[i] = 0.f;
    float rs = 0.f;
    for (int jc = 0; jc < 2; jc++) {
        int jbase = j0 + jc * 128;
        for (int i = tid; i < 128 * NSLOT; i += 256)
            sa[i] = attnT[(b * NTOK + jbase) * NSLOT + i];
        __syncthreads();
        if (tid < NSLOT) {
            float r = 0.f;
            for (int jj = 0; jj < 128; jj++) r += sa[jj * NSLOT + tid];
            rs += r;
        }
        for (int jj = 0; jj < 128; jj++) {
            float vv = v[(b * NTOK + jbase + jj) * 256 + tid];
#pragma unroll
            for (int i = 0; i < NSLOT; i++) acc[i] += sa[jj * NSLOT + i] * vv;
        }
        __syncthreads();
    }
#pragma unroll
    for (int i = 0; i < NSLOT; i++)
        updp[(p * SROWS + b * NSLOT + i) * 256 + tid] = acc[i];
    if (tid < NSLOT) rsp[p * SROWS + b * NSLOT + tid] = rs;
}

// u = (sum_p updp) / (sum_p rowsum)
__global__ void reduce_u_kernel(const float* __restrict__ updp, const float* __restrict__ rsp,
                                float* __restrict__ u) {
    int idx = blockIdx.x * blockDim.x + threadIdx.x;
    int row = idx >> 8;
    float rss = rsp[row] + rsp[SROWS + row] + rsp[2 * SROWS + row] + rsp[3 * SROWS + row];
    float val = updp[idx] + updp[SROWS * 256 + idx] + updp[2 * SROWS * 256 + idx] + updp[3 * SROWS * 256 + idx];
    u[idx] = val / rss;
}

// GRU combine: slots = (1-z)*tanh(i_n + r*h_n) + z*h  (in-place on slots)
__global__ void gru_combine_kernel(const float* __restrict__ gi, const float* __restrict__ gh,
                                   float* __restrict__ slots) {
    int idx = blockIdx.x * blockDim.x + threadIdx.x;
    int row = idx >> 8, col = idx & 255;
    int base = row * 768 + col;
    float r = 1.0f / (1.0f + __expf(-(gi[base] + gh[base])));
    float z = 1.0f / (1.0f + __expf(-(gi[base + 256] + gh[base + 256])));
    float nn = tanhf(gi[base + 512] + r * gh[base + 512]);
    float h = slots[idx];
    slots[idx] = (1.0f - z) * nn + z * h;
}

__global__ void add_kernel(float* __restrict__ slots, const float* __restrict__ ff) {
    int idx = blockIdx.x * blockDim.x + threadIdx.x;
    slots[idx] += ff[idx];
}

__global__ void copy_out_kernel(const float* __restrict__ slots, float* __restrict__ out) {
    int idx = blockIdx.x * blockDim.x + threadIdx.x;
    out[idx] = slots[idx];
}

extern "C" void kernel_launch(void* const* d_in, const int* in_sizes, int n_in,
                              void* d_out, int out_size) {
    const float* inputs    = (const float*)d_in[0];
    const float* noise     = (const float*)d_in[1];
    const float* slots_mu  = (const float*)d_in[2];
    const float* slots_ls  = (const float*)d_in[3];
    const float* Wq        = (const float*)d_in[4];
    const float* Wk        = (const float*)d_in[5];
    const float* Wv        = (const float*)d_in[6];
    const float* gru_wih   = (const float*)d_in[7];
    const float* gru_whh   = (const float*)d_in[8];
    const float* gru_bih   = (const float*)d_in[9];
    const float* gru_bhh   = (const float*)d_in[10];
    const float* mlp_w1    = (const float*)d_in[11];
    const float* mlp_b1    = (const float*)d_in[12];
    const float* mlp_w2    = (const float*)d_in[13];
    const float* mlp_b2    = (const float*)d_in[14];
    const float* ln_in_g   = (const float*)d_in[15];
    const float* ln_in_b   = (const float*)d_in[16];
    const float* ln_s_g    = (const float*)d_in[17];
    const float* ln_s_b    = (const float*)d_in[18];
    const float* ln_ff_g   = (const float*)d_in[19];
    const float* ln_ff_b   = (const float*)d_in[20];

    float* S = nullptr;
    cudaGetSymbolAddress((void**)&S, g_scratch);
    float* stats = S + OFF_STATS;
    float* kbuf  = S + OFF_K;
    float* vbuf  = S + OFF_V;
    float* slots = S + OFF_SLOTS;
    float* sln   = S + OFF_SLN;
    float* qbuf  = S + OFF_Q;
    float* attnT = S + OFF_ATTN;
    float* updp  = S + OFF_UPDP;
    float* rsp   = S + OFF_RSP;
    float* ubuf  = S + OFF_U;
    float* gi    = S + OFF_GI;
    float* gh    = S + OFF_GH;
    float* h1    = S + OFF_H1;
    float* ff    = S + OFF_FF;

    init_slots_kernel<<<256, 256>>>(slots_mu, slots_ls, noise, slots);
    ln_stats_kernel<<<TOKROWS, 256>>>(inputs, stats);
    kv_gemm_kernel<<<dim3(4, 512), 256>>>(inputs, stats, ln_in_g, ln_in_b, Wk, Wv, kbuf, vbuf);

    for (int it = 0; it < ITERS; it++) {
        ln_rows_kernel<<<SROWS, 256>>>(slots, sln, ln_s_g, ln_s_b);
        gemm_nt_kernel<false><<<dim3(4, 4), 256>>>(sln, Wq, nullptr, qbuf, 256, 256, 256);
        dots_softmax_kernel<<<dim3(32, 128), 256>>>(qbuf, kbuf, attnT);
        updates_part_kernel<<<dim3(32, 4), 256>>>(attnT, vbuf, updp, rsp);
        reduce_u_kernel<<<256, 256>>>(updp, rsp, ubuf);
        gemm_nt_kernel<false><<<dim3(12, 4), 256>>>(ubuf, gru_wih, gru_bih, gi, 256, 768, 256);
        gemm_nt_kernel<false><<<dim3(12, 4), 256>>>(slots, gru_whh, gru_bhh, gh, 256, 768, 256);
        gru_combine_kernel<<<256, 256>>>(gi, gh, slots);
        ln_rows_kernel<<<SROWS, 256>>>(slots, sln, ln_ff_g, ln_ff_b);
        gemm_nt_kernel<true><<<dim3(16, 4), 256>>>(sln, mlp_w1, mlp_b1, h1, 256, 1024, 256);
        gemm_nt_kernel<false><<<dim3(4, 4), 256>>>(h1, mlp_w2, mlp_b2, ff, 256, 256, 1024);
        add_kernel<<<256, 256>>>(slots, ff);
    }
    copy_out_kernel<<<256, 256>>>(slots, (float*)d_out);
}

// round 2
// speedup vs baseline: 2.4079x; 2.4079x over previous
#include <cuda_runtime.h>
#include <math.h>

// ---------------------------------------------------------------------------
// SlotAttention: b=32, n=1024, c=256, d=256, S=8 slots, 3 iters.
// KV projection on tf32 tensor cores; small per-iter GEMMs fused SIMT.
// ---------------------------------------------------------------------------
#define Bsz 32
#define NTOK 1024
#define NSLOT 8
#define ITERS 3
#define TOKROWS (Bsz*NTOK)      // 32768
#define SROWS (Bsz*NSLOT)       // 256
#define SCALE_F 0.0625f
#define EPS_F 1e-8f

// scratch arena (floats)
#define OFF_STATS   0                           // 32768*2
#define OFF_STATS_S (OFF_STATS + TOKROWS*2)     // 256*2
#define OFF_K       (OFF_STATS_S + SROWS*2)
#define OFF_V       (OFF_K + TOKROWS*256)
#define OFF_SLOTS   (OFF_V + TOKROWS*256)
#define OFF_GBUF    (OFF_SLOTS + SROWS*256)
#define OFF_Q       (OFF_GBUF + SROWS*256)
#define OFF_ATTN    (OFF_Q + SROWS*256)         // 32*1024*8
#define OFF_UPDP    (OFF_ATTN + Bsz*NTOK*NSLOT) // 4*256*256
#define OFF_RSP     (OFF_UPDP + 4*SROWS*256)    // 4*256
#define OFF_H1      (OFF_RSP + 4*SROWS)         // 256*1024
#define SCRATCH_FLOATS (OFF_H1 + SROWS*1024)

__device__ float g_scratch[SCRATCH_FLOATS];

__device__ __forceinline__ float warp_sum(float v) {
#pragma unroll
    for (int o = 16; o > 0; o >>= 1) v += __shfl_xor_sync(0xffffffffu, v, o);
    return v;
}

__device__ __forceinline__ float f2tf(float x) {
    asm("cvt.rna.tf32.f32 %0, %0;" : "+f"(x));
    return x;
}

__device__ __forceinline__ void mma8(float* d, const unsigned* a, const unsigned* b) {
    asm volatile("mma.sync.aligned.m16n8k8.row.col.f32.tf32.tf32.f32 "
        "{%0,%1,%2,%3}, {%4,%5,%6,%7}, {%8,%9}, {%0,%1,%2,%3};"
        : "+f"(d[0]), "+f"(d[1]), "+f"(d[2]), "+f"(d[3])
        : "r"(a[0]), "r"(a[1]), "r"(a[2]), "r"(a[3]), "r"(b[0]), "r"(b[1]));
}

__device__ __forceinline__ float sigmoidf_(float x) {
    return 1.0f / (1.0f + __expf(-x));
}

// slots = mu + exp(log_sigma) * noise
__global__ void init_slots_kernel(const float* __restrict__ mu,
                                  const float* __restrict__ ls,
                                  const float* __restrict__ noise,
                                  float* __restrict__ slots) {
    int idx = blockIdx.x * blockDim.x + threadIdx.x;
    int d = idx & 255;
    slots[idx] = mu[d] + __expf(ls[d]) * noise[idx];
}

// per-row mean/rstd over 256-wide rows (one warp per row, 8 rows per block)
__global__ void row_stats_kernel(const float* __restrict__ in, float* __restrict__ st) {
    int t = threadIdx.x;
    int row = blockIdx.x * 8 + (t >> 5);
    int lane = t & 31;
    const float* p = in + (size_t)row * 256;
    float s = 0.f, s2 = 0.f;
#pragma unroll
    for (int u = 0; u < 8; u++) { float v = p[lane + u * 32]; s += v; s2 += v * v; }
    s = warp_sum(s); s2 = warp_sum(s2);
    if (lane == 0) {
        float m = s * (1.0f / 256.0f);
        float var = s2 * (1.0f / 256.0f) - m * m;
        st[row * 2] = m;
        st[row * 2 + 1] = rsqrtf(var + 1e-5f);
    }
}

// ---------------------------------------------------------------------------
// tf32 MMA GEMM: C[M=32768, 256] = LN(x)[.,256] @ W[256,256]^T
// BM=128 BN=128 BK=32; warps 2(M)x4(N); warp tile 64x32; m16n8k8 tf32.
// ---------------------------------------------------------------------------
__global__ __launch_bounds__(256) void kv_mma_kernel(
    const float* __restrict__ x, const float* __restrict__ stats,
    const float* __restrict__ lng, const float* __restrict__ lnb,
    const float* __restrict__ W, float* __restrict__ C) {
    __shared__ float As[128][36];
    __shared__ float Bs[128][36];
    int t = threadIdx.x;
    int bm = blockIdx.y * 128, bn = blockIdx.x * 128;
    int w = t >> 5, lane = t & 31;
    int m0 = (w >> 2) * 64, n0 = (w & 3) * 32;
    int g = lane >> 2, tig = lane & 3;

    float acc[4][4][4];
#pragma unroll
    for (int a = 0; a < 4; a++)
#pragma unroll
        for (int b = 0; b < 4; b++)
#pragma unroll
            for (int c = 0; c < 4; c++) acc[a][b][c] = 0.f;

    int lm = t >> 3;          // 0..31
    int lk = (t & 7) * 4;     // 0..28

    for (int k0 = 0; k0 < 256; k0 += 32) {
#pragma unroll
        for (int r = 0; r < 4; r++) {
            int m = r * 32 + lm;
            int row = bm + m, c = k0 + lk;
            float4 xv = *(const float4*)(x + (size_t)row * 256 + c);
            float mv = stats[2 * row], rs = stats[2 * row + 1];
            float4 o;
            o.x = f2tf((xv.x - mv) * rs * lng[c + 0] + lnb[c + 0]);
            o.y = f2tf((xv.y - mv) * rs * lng[c + 1] + lnb[c + 1]);
            o.z = f2tf((xv.z - mv) * rs * lng[c + 2] + lnb[c + 2]);
            o.w = f2tf((xv.w - mv) * rs * lng[c + 3] + lnb[c + 3]);
            *(float4*)&As[m][lk] = o;
            float4 wv = *(const float4*)(W + (size_t)(bn + m) * 256 + c);
            float4 ow;
            ow.x = f2tf(wv.x); ow.y = f2tf(wv.y); ow.z = f2tf(wv.z); ow.w = f2tf(wv.w);
            *(float4*)&Bs[m][lk] = ow;
        }
        __syncthreads();
#pragma unroll
        for (int ks = 0; ks < 32; ks += 8) {
            unsigned a[4][4], b[4][2];
#pragma unroll
            for (int mt = 0; mt < 4; mt++) {
                int mr = m0 + mt * 16 + g;
                a[mt][0] = __float_as_uint(As[mr][ks + tig]);
                a[mt][1] = __float_as_uint(As[mr + 8][ks + tig]);
                a[mt][2] = __float_as_uint(As[mr][ks + tig + 4]);
                a[mt][3] = __float_as_uint(As[mr + 8][ks + tig + 4]);
            }
#pragma unroll
            for (int nt = 0; nt < 4; nt++) {
                int nr = n0 + nt * 8 + g;
                b[nt][0] = __float_as_uint(Bs[nr][ks + tig]);
                b[nt][1] = __float_as_uint(Bs[nr][ks + tig + 4]);
            }
#pragma unroll
            for (int mt = 0; mt < 4; mt++)
#pragma unroll
                for (int nt = 0; nt < 4; nt++)
                    mma8(acc[mt][nt], a[mt], b[nt]);
        }
        __syncthreads();
    }
#pragma unroll
    for (int mt = 0; mt < 4; mt++)
#pragma unroll
        for (int nt = 0; nt < 4; nt++) {
            int row = bm + m0 + mt * 16 + g;
            int col = bn + n0 + nt * 8 + tig * 2;
            *(float2*)(C + (size_t)row * 256 + col) = make_float2(acc[mt][nt][0], acc[mt][nt][1]);
            *(float2*)(C + (size_t)(row + 8) * 256 + col) = make_float2(acc[mt][nt][2], acc[mt][nt][3]);
        }
}

// ---------------------------------------------------------------------------
// small SIMT GEMM: C[M,N] = op(A)[M,K] @ B[N,K]^T (+bias, relu, +addsrc)
// BM=BN=64 BK=32, 256 threads, 4x4 per thread, conflict-free padded smem.
// ---------------------------------------------------------------------------
template<bool LNA, bool RELU, bool ADDOUT>
__global__ __launch_bounds__(256) void gemm_small_kernel(
    const float* __restrict__ A, const float* __restrict__ stats,
    const float* __restrict__ lng, const float* __restrict__ lnb,
    const float* __restrict__ B, const float* __restrict__ bias,
    const float* __restrict__ addsrc, float* __restrict__ C,
    int M, int N, int K) {
    __shared__ float As[32][68];
    __shared__ float Bs[32][68];
    int t = threadIdx.x;
    int bm = blockIdx.y * 64, bn = blockIdx.x * 64;
    int tr = t >> 4, tc = t & 15;
    float acc[4][4];
#pragma unroll
    for (int i = 0; i < 4; i++)
#pragma unroll
        for (int j = 0; j < 4; j++) acc[i][j] = 0.f;

    int lm = t >> 3, lk = (t & 7) * 4;
    for (int k0 = 0; k0 < K; k0 += 32) {
#pragma unroll
        for (int r = 0; r < 2; r++) {
            int m = r * 32 + lm;
            int row = bm + m, c = k0 + lk;
            float4 av = *(const float4*)(A + (size_t)row * K + c);
            if (LNA) {
                float mv = stats[2 * row], rs = stats[2 * row + 1];
                av.x = (av.x - mv) * rs * lng[c + 0] + lnb[c + 0];
                av.y = (av.y - mv) * rs * lng[c + 1] + lnb[c + 1];
                av.z = (av.z - mv) * rs * lng[c + 2] + lnb[c + 2];
                av.w = (av.w - mv) * rs * lng[c + 3] + lnb[c + 3];
            }
            As[lk + 0][m] = av.x; As[lk + 1][m] = av.y; As[lk + 2][m] = av.z; As[lk + 3][m] = av.w;
            float4 bv = *(const float4*)(B + (size_t)(bn + m) * K + c);
            Bs[lk + 0][m] = bv.x; Bs[lk + 1][m] = bv.y; Bs[lk + 2][m] = bv.z; Bs[lk + 3][m] = bv.w;
        }
        __syncthreads();
#pragma unroll
        for (int kk = 0; kk < 32; kk++) {
            float4 a4 = *(float4*)&As[kk][tr * 4];
            float4 b4 = *(float4*)&Bs[kk][tc * 4];
            float a[4] = {a4.x, a4.y, a4.z, a4.w};
            float b[4] = {b4.x, b4.y, b4.z, b4.w};
#pragma unroll
            for (int i = 0; i < 4; i++)
#pragma unroll
                for (int j = 0; j < 4; j++) acc[i][j] += a[i] * b[j];
        }
        __syncthreads();
    }
#pragma unroll
    for (int i = 0; i < 4; i++)
#pragma unroll
        for (int j = 0; j < 4; j++) {
            int row = bm + tr * 4 + i, col = bn + tc * 4 + j;
            float v = acc[i][j];
            if (bias) v += bias[col];
            if (RELU) v = fmaxf(v, 0.f);
            if (ADDOUT) v += addsrc[(size_t)row * N + col];
            C[(size_t)row * N + col] = v;
        }
}

// dots + softmax over slots; attnT[b][j][i] = softmax_i + EPS
__global__ void dots_softmax_kernel(const float* __restrict__ q, const float* __restrict__ k,
                                    float* __restrict__ attnT) {
    int b = blockIdx.x;
    int tid = threadIdx.x;
    __shared__ float qs[NSLOT * 256];
    for (int i = tid; i < NSLOT * 256; i += 256) qs[i] = q[b * NSLOT * 256 + i] * SCALE_F;
    __syncthreads();
    int wid = tid >> 5, lane = tid & 31;
    int j = blockIdx.y * 8 + wid;
    const float* krow = &k[((size_t)b * NTOK + j) * 256];
    float kr[8];
#pragma unroll
    for (int u = 0; u < 8; u++) kr[u] = krow[u * 32 + lane];
    float dv[NSLOT];
#pragma unroll
    for (int i = 0; i < NSLOT; i++) {
        float p = 0.f;
#pragma unroll
        for (int u = 0; u < 8; u++) p += qs[i * 256 + u * 32 + lane] * kr[u];
        dv[i] = warp_sum(p);
    }
    float mx = dv[0];
#pragma unroll
    for (int i = 1; i < NSLOT; i++) mx = fmaxf(mx, dv[i]);
    float se = 0.f, ev[NSLOT];
#pragma unroll
    for (int i = 0; i < NSLOT; i++) { ev[i] = __expf(dv[i] - mx); se += ev[i]; }
    float inv = 1.0f / se;
    float my = 0.f;
#pragma unroll
    for (int i = 0; i < NSLOT; i++) {
        float a = ev[i] * inv + EPS_F;
        if (lane == i) my = a;
    }
    if (lane < NSLOT) attnT[((size_t)b * NTOK + j) * NSLOT + lane] = my;
}

// partial updates over 256-token j ranges + partial row sums
__global__ void updates_part_kernel(const float* __restrict__ attnT, const float* __restrict__ v,
                                    float* __restrict__ updp, float* __restrict__ rsp) {
    int b = blockIdx.x;
    int p = blockIdx.y;
    int tid = threadIdx.x;
    int j0 = p * 256;
    __shared__ float sa[128 * NSLOT];
    float acc[NSLOT];
#pragma unroll
    for (int i = 0; i < NSLOT; i++) acc[i] = 0.f;
    float rs = 0.f;
    for (int jc = 0; jc < 2; jc++) {
        int jbase = j0 + jc * 128;
        for (int i = tid; i < 128 * NSLOT; i += 256)
            sa[i] = attnT[((size_t)b * NTOK + jbase) * NSLOT + i];
        __syncthreads();
        if (tid < NSLOT) {
            float r = 0.f;
            for (int jj = 0; jj < 128; jj++) r += sa[jj * NSLOT + tid];
            rs += r;
        }
        for (int jj = 0; jj < 128; jj++) {
            float vv = v[((size_t)b * NTOK + jbase + jj) * 256 + tid];
#pragma unroll
            for (int i = 0; i < NSLOT; i++) acc[i] += sa[jj * NSLOT + i] * vv;
        }
        __syncthreads();
    }
#pragma unroll
    for (int i = 0; i < NSLOT; i++)
        updp[((size_t)(p * SROWS) + b * NSLOT + i) * 256 + tid] = acc[i];
    if (tid < NSLOT) rsp[p * SROWS + b * NSLOT + tid] = rs;
}

// ---------------------------------------------------------------------------
// fused GRU: reduces updp/rsp -> u, computes gi=u@wih^T, gh=h@whh^T for all
// 3 gates, applies GRU nonlinearity, writes out. BM=BN=32, grid (8,8).
// ---------------------------------------------------------------------------
__global__ __launch_bounds__(256) void gru_fused_kernel(
    const float* __restrict__ updp, const float* __restrict__ rsp,
    const float* __restrict__ slots,
    const float* __restrict__ wih, const float* __restrict__ whh,
    const float* __restrict__ bih, const float* __restrict__ bhh,
    float* __restrict__ out) {
    __shared__ float Au[32][36], Ah[32][36];
    __shared__ float Bg[6][32][36];
    __shared__ float invrs[32];
    int t = threadIdx.x;
    int bm = blockIdx.y * 32, bn = blockIdx.x * 32;
    if (t < 32) {
        int row = bm + t;
        invrs[t] = 1.0f / (rsp[row] + rsp[256 + row] + rsp[512 + row] + rsp[768 + row]);
    }
    __syncthreads();
    float acc[6][2][2];
#pragma unroll
    for (int gb = 0; gb < 6; gb++)
#pragma unroll
        for (int i = 0; i < 2; i++)
#pragma unroll
            for (int j = 0; j < 2; j++) acc[gb][i][j] = 0.f;
    int tr = t >> 4, tc = t & 15;
    int lm = t >> 3, lk = (t & 7) * 4;

    for (int k0 = 0; k0 < 256; k0 += 32) {
        {
            int row = bm + lm, c = k0 + lk;
            float inv = invrs[lm];
            float4 u0 = *(const float4*)(updp + (size_t)row * 256 + c);
            float4 u1 = *(const float4*)(updp + 65536 + (size_t)row * 256 + c);
            float4 u2 = *(const float4*)(updp + 131072 + (size_t)row * 256 + c);
            float4 u3 = *(const float4*)(updp + 196608 + (size_t)row * 256 + c);
            Au[lk + 0][lm] = (u0.x + u1.x + u2.x + u3.x) * inv;
            Au[lk + 1][lm] = (u0.y + u1.y + u2.y + u3.y) * inv;
            Au[lk + 2][lm] = (u0.z + u1.z + u2.z + u3.z) * inv;
            Au[lk + 3][lm] = (u0.w + u1.w + u2.w + u3.w) * inv;
            float4 h4 = *(const float4*)(slots + (size_t)row * 256 + c);
            Ah[lk + 0][lm] = h4.x; Ah[lk + 1][lm] = h4.y; Ah[lk + 2][lm] = h4.z; Ah[lk + 3][lm] = h4.w;
#pragma unroll
            for (int gb = 0; gb < 6; gb++) {
                const float* W = (gb < 3) ? wih : whh;
                int wr = bn + lm + (gb % 3) * 256;
                float4 w4 = *(const float4*)(W + (size_t)wr * 256 + c);
                Bg[gb][lk + 0][lm] = w4.x; Bg[gb][lk + 1][lm] = w4.y;
                Bg[gb][lk + 2][lm] = w4.z; Bg[gb][lk + 3][lm] = w4.w;
            }
        }
        __syncthreads();
#pragma unroll
        for (int kk = 0; kk < 32; kk++) {
            float2 au = *(float2*)&Au[kk][tr * 2];
            float2 ah = *(float2*)&Ah[kk][tr * 2];
            float aus[2] = {au.x, au.y};
            float ahs[2] = {ah.x, ah.y};
#pragma unroll
            for (int gb = 0; gb < 6; gb++) {
                float2 bg = *(float2*)&Bg[gb][kk][tc * 2];
                float bs[2] = {bg.x, bg.y};
                const float* a = (gb < 3) ? aus : ahs;
#pragma unroll
                for (int i = 0; i < 2; i++)
#pragma unroll
                    for (int j = 0; j < 2; j++) acc[gb][i][j] += a[i] * bs[j];
            }
        }
        __syncthreads();
    }
#pragma unroll
    for (int i = 0; i < 2; i++)
#pragma unroll
        for (int j = 0; j < 2; j++) {
            int row = bm + tr * 2 + i, col = bn + tc * 2 + j;
            float ir = acc[0][i][j] + bih[col];
            float iz = acc[1][i][j] + bih[col + 256];
            float in_ = acc[2][i][j] + bih[col + 512];
            float hr = acc[3][i][j] + bhh[col];
            float hz = acc[4][i][j] + bhh[col + 256];
            float hn = acc[5][i][j] + bhh[col + 512];
            float r = sigmoidf_(ir + hr);
            float z = sigmoidf_(iz + hz);
            float nn = tanhf(in_ + r * hn);
            float h = slots[(size_t)row * 256 + col];
            out[(size_t)row * 256 + col] = (1.0f - z) * nn + z * h;
        }
}

extern "C" void kernel_launch(void* const* d_in, const int* in_sizes, int n_in,
                              void* d_out, int out_size) {
    const float* inputs    = (const float*)d_in[0];
    const float* noise     = (const float*)d_in[1];
    const float* slots_mu  = (const float*)d_in[2];
    const float* slots_ls  = (const float*)d_in[3];
    const float* Wq        = (const float*)d_in[4];
    const float* Wk        = (const float*)d_in[5];
    const float* Wv        = (const float*)d_in[6];
    const float* gru_wih   = (const float*)d_in[7];
    const float* gru_whh   = (const float*)d_in[8];
    const float* gru_bih   = (const float*)d_in[9];
    const float* gru_bhh   = (const float*)d_in[10];
    const float* mlp_w1    = (const float*)d_in[11];
    const float* mlp_b1    = (const float*)d_in[12];
    const float* mlp_w2    = (const float*)d_in[13];
    const float* mlp_b2    = (const float*)d_in[14];
    const float* ln_in_g   = (const float*)d_in[15];
    const float* ln_in_b   = (const float*)d_in[16];
    const float* ln_s_g    = (const float*)d_in[17];
    const float* ln_s_b    = (const float*)d_in[18];
    const float* ln_ff_g   = (const float*)d_in[19];
    const float* ln_ff_b   = (const float*)d_in[20];

    float* S = nullptr;
    cudaGetSymbolAddress((void**)&S, g_scratch);
    float* stats = S + OFF_STATS;
    float* statS = S + OFF_STATS_S;
    float* kbuf  = S + OFF_K;
    float* vbuf  = S + OFF_V;
    float* slots = S + OFF_SLOTS;
    float* gbuf  = S + OFF_GBUF;
    float* qbuf  = S + OFF_Q;
    float* attnT = S + OFF_ATTN;
    float* updp  = S + OFF_UPDP;
    float* rsp   = S + OFF_RSP;
    float* h1    = S + OFF_H1;

    // launches 0..5 arranged so ncu (-s 5 -c 1) captures the V mma GEMM
    init_slots_kernel<<<256, 256>>>(slots_mu, slots_ls, noise, slots);       // 0
    row_stats_kernel<<<TOKROWS / 8, 256>>>(inputs, stats);                   // 1
    row_stats_kernel<<<SROWS / 8, 256>>>(slots, statS);                      // 2
    gemm_small_kernel<true, false, false><<<dim3(4, 4), 256>>>(              // 3: q
        slots, statS, ln_s_g, ln_s_b, Wq, nullptr, nullptr, qbuf, 256, 256, 256);
    kv_mma_kernel<<<dim3(2, 256), 256>>>(inputs, stats, ln_in_g, ln_in_b, Wk, kbuf); // 4
    kv_mma_kernel<<<dim3(2, 256), 256>>>(inputs, stats, ln_in_g, ln_in_b, Wv, vbuf); // 5

    for (int it = 0; it < ITERS; it++) {
        if (it > 0) {
            row_stats_kernel<<<SROWS / 8, 256>>>(slots, statS);
            gemm_small_kernel<true, false, false><<<dim3(4, 4), 256>>>(
                slots, statS, ln_s_g, ln_s_b, Wq, nullptr, nullptr, qbuf, 256, 256, 256);
        }
        dots_softmax_kernel<<<dim3(32, 128), 256>>>(qbuf, kbuf, attnT);
        updates_part_kernel<<<dim3(32, 4), 256>>>(attnT, vbuf, updp, rsp);
        gru_fused_kernel<<<dim3(8, 8), 256>>>(updp, rsp, slots,
            gru_wih, gru_whh, gru_bih, gru_bhh, gbuf);
        row_stats_kernel<<<SROWS / 8, 256>>>(gbuf, statS);
        gemm_small_kernel<true, true, false><<<dim3(16, 4), 256>>>(
            gbuf, statS, ln_ff_g, ln_ff_b, mlp_w1, mlp_b1, nullptr, h1, 256, 1024, 256);
        float* outp = (it == ITERS - 1) ? (float*)d_out : slots;
        gemm_small_kernel<false, false, true><<<dim3(4, 4), 256>>>(
            h1, nullptr, nullptr, nullptr, mlp_w2, mlp_b2, gbuf, outp, 256, 256, 1024);
    }
}